// round 15
// baseline (speedup 1.0000x reference)
#include <cuda_runtime.h>
#include <math.h>

// Problem constants
#define BB      8
#define HH      384
#define WW      384
#define NN      96
#define NSEG    (NN - 1)
#define HWSZ    (HH * WW)
#define STEPSZ  0.1f
#define ALPHA_C 0.01f
#define BETA_C  0.01f
#define NSTEPS  50
#define NSTEPS_W 10
#define DMAX_C  15.0f
#define EXTF    10.0f

// Conv tiling
#define CT   32
#define CRAW 38
#define CS   41
#define CTX  (WW / CT)   // 12
#define CTY  (HH / CT)   // 12

// Render tiling: 32x32 px tiles, 2x2 px per thread
#define TDIM          32
#define TILES_X       (WW / TDIM)              // 12
#define TILES_Y       (HH / TDIM)              // 12
#define BLKS_PER_IMG  (TILES_X * TILES_Y)      // 144
#define RENDER_TASKS  (BB * BLKS_PER_IMG)      // 1152
#define TILE_RAD      21.95f

// Task queue: per batch 144 conv + 1 snake; then all renders
#define TASKS_PER_BATCH 145
#define CONVSNAKE_TASKS (BB * TASKS_PER_BATCH)            // 1160
#define NTASKS          (CONVSNAKE_TASKS + RENDER_TASKS)  // 2312

#define MEGA_BLOCKS 1152
#define MEGA_TPB    256

#define FLAG_STRIDE 32
#define FULLMASK 0xffffffffu

// ---------------- device scratch ----------------
__device__ float  g_g [BB * 2 * HWSZ];
__device__ float  g_gw[BB * 2 * HWSZ];
__device__ float4 g_segs[BB * NSEG * 3];
__device__ float  g_part[RENDER_TASKS];
__device__ unsigned int g_task;
__device__ unsigned int g_cnt;
__device__ unsigned int g_convdone[BB * FLAG_STRIDE];
__device__ unsigned int g_segdone [BB * FLAG_STRIDE];

// ---------------- shared memory layout (union over phases) -----------------
struct SmemConv {
    float raw[CRAW * CS];
    float pdg[CT * CS];
    float pg [CT * CS];
    float adg[CT * CS];
    float ag [CT * CS];
    float g1[7], dg1[7];
};
struct SmemSnake {
    float xs[2][NN][2];
    float wsh[NN];
};
struct SmemRender {
    double sd[MEGA_TPB];
    float4 ksA[NSEG];
    float4 ksB[NSEG];
    float  ksW[NSEG];
    float  wsum[MEGA_TPB / 32];
};
union SmemAll {
    SmemConv   c;
    SmemSnake  s;
    SmemRender r;
};

// ---------------- reset node ----------------
__global__ void reset_kernel() {
    g_task = 0u;
    g_cnt  = 0u;
#pragma unroll
    for (int b = 0; b < BB; b++) {
        g_convdone[b * FLAG_STRIDE] = 0u;
        g_segdone [b * FLAG_STRIDE] = 0u;
    }
}

// ---------------- conv tile ----------------
__device__ __forceinline__ void conv_tile(const float* __restrict__ pred,
                                          const float* __restrict__ fltr,
                                          int b, int bx, int by,
                                          SmemConv& C, int tid) {
    const int x0 = bx * CT, y0 = by * CT;
    const int ty = tid >> 5;
    const int tx = tid & 31;

    if (tid < 7) {
        float sg = 0.f, sd = 0.f;
#pragma unroll
        for (int k = 0; k < 7; k++) {
            sg += fabsf(fltr[k * 7 + tid]);
            sd += fltr[tid * 7 + k];
        }
        C.g1[tid] = sg;
        C.dg1[tid] = sd;
    }

    const float* img = pred + (size_t)b * HWSZ;
    const bool interior = (bx >= 1) && (bx <= CTX - 2) && (by >= 1) && (by <= CTY - 2);
    if (interior) {
        const float* src = img + (y0 - 3) * WW + (x0 - 3);
#pragma unroll
        for (int rr = 0; rr < 5; rr++) {
            int r = ty + rr * 8;
            if (r < CRAW) {
                float*       dst = C.raw + r * CS;
                const float* sr  = src   + r * WW;
                dst[tx] = sr[tx];
                if (tx < CRAW - 32) dst[tx + 32] = sr[tx + 32];
            }
        }
    } else {
        for (int i = tid; i < CRAW * CRAW; i += MEGA_TPB) {
            int sy = i / CRAW, sx = i % CRAW;
            int gy = y0 + sy - 3, gx = x0 + sx - 3;
            float v = 0.0f;
            if (gy >= 0 && gy < HH && gx >= 0 && gx < WW) v = img[gy * WW + gx];
            C.raw[sy * CS + sx] = v;
        }
    }
    __syncthreads();

    float rg[7], rdg[7];
#pragma unroll
    for (int k = 0; k < 7; k++) { rg[k] = C.g1[k]; rdg[k] = C.dg1[k]; }

#pragma unroll
    for (int rr = 0; rr < 4; rr++) {
        int r = ty + rr * 8;
#pragma unroll
        for (int half = 0; half < 2; half++) {
            int c = tx + half * 32;
            if (half == 1 && tx >= CRAW - 32) break;
            float pdg = 0.f, pg = 0.f, adg = 0.f, ag = 0.f;
#pragma unroll
            for (int k = 0; k < 7; k++) {
                float v = C.raw[(r + k) * CS + c];
                float a = fabsf(v);
                pdg = fmaf(rdg[k], v, pdg);
                pg  = fmaf(rg[k],  v, pg);
                adg = fmaf(rdg[k], a, adg);
                ag  = fmaf(rg[k],  a, ag);
            }
            C.pdg[r * CS + c] = pdg;
            C.pg [r * CS + c] = pg;
            C.adg[r * CS + c] = adg;
            C.ag [r * CS + c] = ag;
        }
    }
    __syncthreads();

    const int r  = tid >> 3;
    const int cb = (tid & 7) * 4;
    float wpd[10], wpg[10], wad[10], wag[10];
#pragma unroll
    for (int j = 0; j < 10; j++) {
        wpd[j] = C.pdg[r * CS + cb + j];
        wpg[j] = C.pg [r * CS + cb + j];
        wad[j] = C.adg[r * CS + cb + j];
        wag[j] = C.ag [r * CS + cb + j];
    }
    float fy0[4], fx0[4], fy1[4], fx1[4];
#pragma unroll
    for (int u = 0; u < 4; u++) {
        float a = 0.f, bz = 0.f, c = 0.f, d = 0.f;
#pragma unroll
        for (int k = 0; k < 7; k++) {
            a = fmaf(rg[k],  wpd[u + k], a);
            bz= fmaf(rdg[k], wpg[u + k], bz);
            c = fmaf(rg[k],  wad[u + k], c);
            d = fmaf(rdg[k], wag[u + k], d);
        }
        fy0[u] = a * EXTF; fx0[u] = bz * EXTF;
        fy1[u] = c * EXTF; fx1[u] = d * EXTF;
    }
    const size_t base = ((size_t)b * HWSZ + (size_t)(y0 + r) * WW + (x0 + cb)) * 2;
    *(float4*)(g_g  + base)     = make_float4(fy0[0], fx0[0], fy0[1], fx0[1]);
    *(float4*)(g_g  + base + 4) = make_float4(fy0[2], fx0[2], fy0[3], fx0[3]);
    *(float4*)(g_gw + base)     = make_float4(fy1[0], fx1[0], fy1[1], fx1[1]);
    *(float4*)(g_gw + base + 4) = make_float4(fy1[2], fx1[2], fy1[3], fx1[3]);
}

// ---------------- bilinear interp of interleaved 2-channel image -----------
__device__ __forceinline__ void interp2(const float2* __restrict__ img,
                                        float py, float px,
                                        float& v0, float& v1) {
    float y = fminf(fmaxf(py, 0.0f), (float)(HH - 1));
    float x = fminf(fmaxf(px, 0.0f), (float)(WW - 1));
    float y0f = floorf(y), x0f = floorf(x);
    int y0 = (int)y0f, x0 = (int)x0f;
    int y1 = min(y0 + 1, HH - 1);
    int x1 = min(x0 + 1, WW - 1);
    float wy = y - y0f, wx = x - x0f;
    float w00 = (1.0f - wy) * (1.0f - wx);
    float w01 = (1.0f - wy) * wx;
    float w10 = wy * (1.0f - wx);
    float w11 = wy * wx;
    float2 a = img[y0 * WW + x0];
    float2 b = img[y0 * WW + x1];
    float2 c = img[y1 * WW + x0];
    float2 d = img[y1 * WW + x1];
    v0 = a.x * w00 + b.x * w01 + c.x * w10 + d.x * w11;
    v1 = a.y * w00 + b.y * w01 + c.y * w10 + d.y * w11;
}

// interp + L1 prefetch of rows y0-1 and y0+2 (likely touched next step)
__device__ __forceinline__ void interp2_pf(const float2* __restrict__ img,
                                           float py, float px,
                                           float& v0, float& v1) {
    float y = fminf(fmaxf(py, 0.0f), (float)(HH - 1));
    float x = fminf(fmaxf(px, 0.0f), (float)(WW - 1));
    float y0f = floorf(y), x0f = floorf(x);
    int y0 = (int)y0f, x0 = (int)x0f;
    int y1 = min(y0 + 1, HH - 1);
    int x1 = min(x0 + 1, WW - 1);
    float wy = y - y0f, wx = x - x0f;
    float w00 = (1.0f - wy) * (1.0f - wx);
    float w01 = (1.0f - wy) * wx;
    float w10 = wy * (1.0f - wx);
    float w11 = wy * wx;
    float2 a = img[y0 * WW + x0];
    float2 b = img[y0 * WW + x1];
    float2 c = img[y1 * WW + x0];
    float2 d = img[y1 * WW + x1];
    v0 = a.x * w00 + b.x * w01 + c.x * w10 + d.x * w11;
    v1 = a.y * w00 + b.y * w01 + c.y * w10 + d.y * w11;
    // prefetch rows above/below for the next step (position moves <~1px/step)
    int ym = max(y0 - 1, 0);
    int yp = min(y0 + 2, HH - 1);
    const float2* pm = img + ym * WW + x0;
    const float2* pp = img + yp * WW + x0;
    asm volatile("prefetch.global.L1 [%0];" :: "l"(pm));
    asm volatile("prefetch.global.L1 [%0];" :: "l"(pp));
}

// ---------------- snake ----------------
__device__ __forceinline__ void snake_run(const float* __restrict__ nodes,
                                          const float* __restrict__ widths,
                                          int b, SmemSnake& S, int tid) {
    const int i = tid;
    const bool act = (i < NN);

    const float2* g  = (const float2*)g_g  + (size_t)b * HWSZ;
    const float2* gw = (const float2*)g_gw + (size_t)b * HWSZ;

    float xy = 0.f, xx = 0.f;
    if (act) {
        xy = nodes[((size_t)b * NN + i) * 2 + 0];
        xx = nodes[((size_t)b * NN + i) * 2 + 1];
        S.xs[0][i][0] = xy; S.xs[0][i][1] = xx;
    }
    __syncthreads();

    const int a2i = max(i - 2, 0), a1 = max(i - 1, 0);
    const int b1 = min(i + 1, NN - 1), b2 = min(i + 2, NN - 1);
    int p = 0;

    for (int s = 0; s < NSTEPS; s++) {
        if (act) {
            float fe0, fe1;
            interp2_pf(g, xy, xx, fe0, fe1);

            float ym2 = S.xs[p][a2i][0], ym1 = S.xs[p][a1][0];
            float yp1 = S.xs[p][b1][0],  yp2 = S.xs[p][b2][0];
            float xm2 = S.xs[p][a2i][1], xm1 = S.xs[p][a1][1];
            float xp1 = S.xs[p][b1][1],  xp2 = S.xs[p][b2][1];

            float d20 = ym1 - 2.0f * xy + yp1;
            float d21 = xm1 - 2.0f * xx + xp1;
            float tm0 = (i >= 1) ? xy : yp1;
            float tm1 = (i >= 1) ? xx : xp1;
            float d2m0 = ym2 - 2.0f * ym1 + tm0;
            float d2m1 = xm2 - 2.0f * xm1 + tm1;
            float tp0 = (i <= NN - 2) ? xy : ym1;
            float tp1 = (i <= NN - 2) ? xx : xm1;
            float d2p0 = tp0 - 2.0f * yp1 + yp2;
            float d2p1 = tp1 - 2.0f * xp1 + xp2;

            float d40 = d2m0 - 2.0f * d20 + d2p0;
            float d41 = d2m1 - 2.0f * d21 + d2p1;

            xy += STEPSZ * (ALPHA_C * d20 - BETA_C * d40 + fe0);
            xx += STEPSZ * (ALPHA_C * d21 - BETA_C * d41 + fe1);
            S.xs[1 - p][i][0] = xy;
            S.xs[1 - p][i][1] = xx;
        }
        __syncthreads();
        p ^= 1;
    }

    if (act) {
        float t0, t1;
        if (i == 0)            { t0 = S.xs[p][1][0] - S.xs[p][0][0];           t1 = S.xs[p][1][1] - S.xs[p][0][1]; }
        else if (i == NN - 1)  { t0 = S.xs[p][NN-1][0] - S.xs[p][NN-2][0];     t1 = S.xs[p][NN-1][1] - S.xs[p][NN-2][1]; }
        else                   { t0 = 0.5f * (S.xs[p][i+1][0] - S.xs[p][i-1][0]); t1 = 0.5f * (S.xs[p][i+1][1] - S.xs[p][i-1][1]); }
        float n0 = -t1, n1 = t0;
        float nrm = sqrtf(n0 * n0 + n1 * n1) + 1e-6f;
        n0 /= nrm; n1 /= nrm;

        float w = widths[(size_t)b * NN + i];
        for (int s = 0; s < NSTEPS_W; s++) {
            float gp0, gp1, gm0, gm1;
            interp2_pf(gw, xy + w * n0, xx + w * n1, gp0, gp1);
            interp2_pf(gw, xy - w * n0, xx - w * n1, gm0, gm1);
            float f = 0.5f * ((gp0 * n0 + gp1 * n1) - (gm0 * n0 + gm1 * n1));
            w = fmaxf(w + STEPSZ * f, 0.5f);
        }
        S.wsh[i] = w;
    }
    __syncthreads();

    if (i < NSEG) {
        float ay = S.xs[p][i][0],   ax = S.xs[p][i][1];
        float by = S.xs[p][i+1][0], bx = S.xs[p][i+1][1];
        float aby = by - ay, abx = bx - ax;
        float den = aby * aby + abx * abx + 1e-8f;
        float aab = ay * aby + ax * abx;
        float a2  = ay * ay + ax * ax;
        float wsg = 0.5f * (S.wsh[i] + S.wsh[i + 1]);
        float4* sp = g_segs + ((size_t)b * NSEG + i) * 3;
        sp[0] = make_float4(aby, abx, aab, 1.0f / den);
        sp[1] = make_float4(den, -2.0f * ay, -2.0f * ax, a2);
        sp[2] = make_float4(wsg, 0.f, 0.f, 0.f);
    }
}

// ---------------- render tile ----------------
__device__ __forceinline__ void render_tile(const float* __restrict__ pred,
                                            float* __restrict__ out,
                                            int b, int bx, int by, int bid,
                                            SmemRender& R, int* s_nk, int* s_last,
                                            int tid) {
    if (tid == 0) *s_nk = 0;
    __syncthreads();

    const float cy = (float)(by * TDIM) + 15.5f;
    const float cx = (float)(bx * TDIM) + 15.5f;
    if (tid < NSEG) {
        const float4* sp = g_segs + ((size_t)b * NSEG + tid) * 3;
        float4 qa = sp[0];
        float4 qb = sp[1];
        float  wsg = sp[2].x;
        float dotpa = fmaf(cy, qa.x, fmaf(cx, qa.y, -qa.z));
        float t = fminf(fmaxf(dotpa * qa.w, 0.0f), 1.0f);
        float pa2 = fmaf(cy, cy, cx * cx) + fmaf(cy, qb.y, fmaf(cx, qb.z, qb.w));
        float dd = fmaf(t, fmaf(t, qb.x, -2.0f * dotpa), pa2);
        float thr = DMAX_C + TILE_RAD + wsg;
        if (dd <= thr * thr) {
            int slot = atomicAdd(s_nk, 1);
            R.ksA[slot] = qa;
            R.ksB[slot] = qb;
            R.ksW[slot] = wsg;
        }
    }
    __syncthreads();
    const int nk = *s_nk;

    const int qy = (tid >> 4);
    const int qx = (tid & 15);
    const int py = by * TDIM + 2 * qy;
    const int px = bx * TDIM + 2 * qx;
    const float fy = (float)py;
    const float fx = (float)px;
    const float p2 = fy * fy + fx * fx;
    const float cx1 = 2.0f * fx + 1.0f;
    const float cy1 = 2.0f * fy + 1.0f;

    float m00 = 3.0e38f, m01 = 3.0e38f, m10 = 3.0e38f, m11 = 3.0e38f;
    for (int s = 0; s < nk; s++) {
        float4 qa = R.ksA[s];
        float4 qb = R.ksB[s];
        float  wsg = R.ksW[s];
        float d00 = fmaf(fy, qa.x, fmaf(fx, qa.y, -qa.z));
        float d01 = d00 + qa.y;
        float d10 = d00 + qa.x;
        float d11 = d10 + qa.y;
        float q00 = p2 + fmaf(fy, qb.y, fmaf(fx, qb.z, qb.w));
        float ex = cx1 + qb.z;
        float ey = cy1 + qb.y;
        float q01 = q00 + ex;
        float q10 = q00 + ey;
        float q11 = q01 + ey;

        float t00 = fminf(fmaxf(d00 * qa.w, 0.0f), 1.0f);
        float t01 = fminf(fmaxf(d01 * qa.w, 0.0f), 1.0f);
        float t10 = fminf(fmaxf(d10 * qa.w, 0.0f), 1.0f);
        float t11 = fminf(fmaxf(d11 * qa.w, 0.0f), 1.0f);

        float e00 = fmaf(t00, fmaf(t00, qb.x, -2.0f * d00), q00);
        float e01 = fmaf(t01, fmaf(t01, qb.x, -2.0f * d01), q01);
        float e10 = fmaf(t10, fmaf(t10, qb.x, -2.0f * d10), q10);
        float e11 = fmaf(t11, fmaf(t11, qb.x, -2.0f * d11), q11);

        // segments with e >= (DMAX+wsg)^2 give d-wsg >= DMAX -> absorbed by
        // the final clip; skipping them is EXACT. Warp-uniform branch.
        float lim = DMAX_C + wsg;
        float lim2 = lim * lim;
        bool need = (e00 < lim2) | (e01 < lim2) | (e10 < lim2) | (e11 < lim2);
        if (__ballot_sync(FULLMASK, need)) {
            e00 = fmaxf(e00, 1e-18f);
            e01 = fmaxf(e01, 1e-18f);
            e10 = fmaxf(e10, 1e-18f);
            e11 = fmaxf(e11, 1e-18f);
            m00 = fminf(m00, fmaf(e00, rsqrtf(e00), -wsg));
            m01 = fminf(m01, fmaf(e01, rsqrtf(e01), -wsg));
            m10 = fminf(m10, fmaf(e10, rsqrtf(e10), -wsg));
            m11 = fminf(m11, fmaf(e11, rsqrtf(e11), -wsg));
        }
    }

    const float* prow0 = pred + (size_t)b * HWSZ + (size_t)py * WW + px;
    float2 p0 = *(const float2*)prow0;
    float2 p1 = *(const float2*)(prow0 + WW);

    float v = 0.f;
    float dm, df;
    dm = fminf(fmaxf(m00, 0.0f), DMAX_C); df = p0.x - dm; v = fmaf(df, df, v);
    dm = fminf(fmaxf(m01, 0.0f), DMAX_C); df = p0.y - dm; v = fmaf(df, df, v);
    dm = fminf(fmaxf(m10, 0.0f), DMAX_C); df = p1.x - dm; v = fmaf(df, df, v);
    dm = fminf(fmaxf(m11, 0.0f), DMAX_C); df = p1.y - dm; v = fmaf(df, df, v);

#pragma unroll
    for (int o = 16; o > 0; o >>= 1) v += __shfl_down_sync(FULLMASK, v, o);
    if ((tid & 31) == 0) R.wsum[tid >> 5] = v;
    __syncthreads();
    if (tid == 0) {
        float s = 0.f;
#pragma unroll
        for (int i = 0; i < MEGA_TPB / 32; i++) s += R.wsum[i];
        g_part[bid] = s;
        __threadfence();
        unsigned old = atomicAdd(&g_cnt, 1u);
        *s_last = (old == RENDER_TASKS - 1) ? 1 : 0;
    }
    __syncthreads();

    if (*s_last) {
        double a = 0.0;
        for (int i = tid; i < RENDER_TASKS; i += MEGA_TPB)
            a += (double)__ldcg(&g_part[i]);
        R.sd[tid] = a;
        __syncthreads();
#pragma unroll
        for (int s = MEGA_TPB / 2; s > 0; s >>= 1) {
            if (tid < s) R.sd[tid] += R.sd[tid + s];
            __syncthreads();
        }
        if (tid == 0)
            out[0] = (float)(R.sd[0] / (double)((size_t)BB * HWSZ));
    }
    __syncthreads();
}

// ================= mega kernel: task-queue pipeline =========================
__global__ void __launch_bounds__(MEGA_TPB)
mega_kernel(const float* __restrict__ pred,
            const float* __restrict__ nodes,
            const float* __restrict__ widths,
            const float* __restrict__ fltr,
            float* __restrict__ out) {
    __shared__ SmemAll sm;
    __shared__ unsigned int s_task;
    __shared__ int s_nk, s_last;
    const int tid = threadIdx.x;

    for (;;) {
        __syncthreads();
        if (tid == 0) s_task = atomicAdd(&g_task, 1u);
        __syncthreads();
        const unsigned int task = s_task;
        if (task >= NTASKS) return;

        if (task < CONVSNAKE_TASKS) {
            const int b = task / TASKS_PER_BATCH;
            const int t = task % TASKS_PER_BATCH;
            if (t < CTX * CTY) {
                conv_tile(pred, fltr, b, t % CTX, t / CTX, sm.c, tid);
                __threadfence();
                __syncthreads();
                if (tid == 0) atomicAdd(&g_convdone[b * FLAG_STRIDE], 1u);
            } else {
                if (tid == 0) {
                    while (__ldcg(&g_convdone[b * FLAG_STRIDE]) < (unsigned)(CTX * CTY))
                        __nanosleep(500);
                }
                __syncthreads();
                __threadfence();
                snake_run(nodes, widths, b, sm.s, tid);
                __threadfence();
                __syncthreads();
                if (tid == 0) atomicExch(&g_segdone[b * FLAG_STRIDE], 1u);
            }
        } else {
            const int r = (int)(task - CONVSNAKE_TASKS);
            const int b = r / BLKS_PER_IMG;
            const int t = r % BLKS_PER_IMG;
            if (tid == 0) {
                while (__ldcg(&g_segdone[b * FLAG_STRIDE]) == 0u)
                    __nanosleep(1000);
            }
            __syncthreads();
            __threadfence();
            render_tile(pred, out, b, t % TILES_X, t / TILES_X, r,
                        sm.r, &s_nk, &s_last, tid);
        }
    }
}

// ---------------- launcher --------------------------------------------------
extern "C" void kernel_launch(void* const* d_in, const int* in_sizes, int n_in,
                              void* d_out, int out_size) {
    const float* pred   = (const float*)d_in[0];
    const float* nodes  = (const float*)d_in[1];
    const float* widths = (const float*)d_in[2];
    const float* fltr   = (const float*)d_in[3];
    float* out = (float*)d_out;

    reset_kernel<<<1, 1>>>();
    mega_kernel<<<MEGA_BLOCKS, MEGA_TPB>>>(pred, nodes, widths, fltr, out);
}

// round 16
// speedup vs baseline: 1.0248x; 1.0248x over previous
#include <cuda_runtime.h>
#include <math.h>

// Problem constants
#define BB      8
#define HH      384
#define WW      384
#define NN      96
#define NSEG    (NN - 1)
#define HWSZ    (HH * WW)
#define STEPSZ  0.1f
#define ALPHA_C 0.01f
#define BETA_C  0.01f
#define NSTEPS  50
#define NSTEPS_W 10
#define DMAX_C  15.0f
#define EXTF    10.0f

// Conv tiling
#define CT   32
#define CRAW 38
#define CS   41
#define CTX  (WW / CT)   // 12
#define CTY  (HH / CT)   // 12

// Render tiling: 32x32 px tiles, 2x2 px per thread
#define TDIM          32
#define TILES_X       (WW / TDIM)              // 12
#define TILES_Y       (HH / TDIM)              // 12
#define BLKS_PER_IMG  (TILES_X * TILES_Y)      // 144
#define RENDER_TASKS  (BB * BLKS_PER_IMG)      // 1152
#define TILE_RAD      21.95f

// Task queue: per batch 144 conv + 1 snake; then all renders
#define TASKS_PER_BATCH 145
#define CONVSNAKE_TASKS (BB * TASKS_PER_BATCH)            // 1160
#define NTASKS          (CONVSNAKE_TASKS + RENDER_TASKS)  // 2312

// THROTTLED: 4 blocks/SM -> ordered queue pipelines batches:
// batch-0 conv done ~4us, snakes overlap later convs, renders fill the tail.
#define MEGA_BLOCKS 592
#define MEGA_TPB    256

#define FLAG_STRIDE 32
#define FULLMASK 0xffffffffu

// ---------------- device scratch ----------------
__device__ float  g_g [BB * 2 * HWSZ];
__device__ float  g_gw[BB * 2 * HWSZ];
__device__ float4 g_segs[BB * NSEG * 3];
__device__ float  g_part[RENDER_TASKS];
__device__ unsigned int g_task;
__device__ unsigned int g_cnt;
__device__ unsigned int g_convdone[BB * FLAG_STRIDE];
__device__ unsigned int g_segdone [BB * FLAG_STRIDE];

// ---------------- shared memory layout (union over phases) -----------------
struct SmemConv {
    float raw[CRAW * CS];
    float pdg[CT * CS];
    float pg [CT * CS];
    float adg[CT * CS];
    float ag [CT * CS];
    float g1[7], dg1[7];
};
struct SmemSnake {
    float xs[2][NN][2];
    float wsh[NN];
};
struct SmemRender {
    double sd[MEGA_TPB];
    float4 ksA[NSEG];
    float4 ksB[NSEG];
    float  ksW[NSEG];
    float  wsum[MEGA_TPB / 32];
};
union SmemAll {
    SmemConv   c;
    SmemSnake  s;
    SmemRender r;
};

// ---------------- reset node ----------------
__global__ void reset_kernel() {
    g_task = 0u;
    g_cnt  = 0u;
#pragma unroll
    for (int b = 0; b < BB; b++) {
        g_convdone[b * FLAG_STRIDE] = 0u;
        g_segdone [b * FLAG_STRIDE] = 0u;
    }
}

// ---------------- conv tile ----------------
__device__ __forceinline__ void conv_tile(const float* __restrict__ pred,
                                          const float* __restrict__ fltr,
                                          int b, int bx, int by,
                                          SmemConv& C, int tid) {
    const int x0 = bx * CT, y0 = by * CT;
    const int ty = tid >> 5;
    const int tx = tid & 31;

    if (tid < 7) {
        float sg = 0.f, sd = 0.f;
#pragma unroll
        for (int k = 0; k < 7; k++) {
            sg += fabsf(fltr[k * 7 + tid]);
            sd += fltr[tid * 7 + k];
        }
        C.g1[tid] = sg;
        C.dg1[tid] = sd;
    }

    const float* img = pred + (size_t)b * HWSZ;
    const bool interior = (bx >= 1) && (bx <= CTX - 2) && (by >= 1) && (by <= CTY - 2);
    if (interior) {
        const float* src = img + (y0 - 3) * WW + (x0 - 3);
#pragma unroll
        for (int rr = 0; rr < 5; rr++) {
            int r = ty + rr * 8;
            if (r < CRAW) {
                float*       dst = C.raw + r * CS;
                const float* sr  = src   + r * WW;
                dst[tx] = sr[tx];
                if (tx < CRAW - 32) dst[tx + 32] = sr[tx + 32];
            }
        }
    } else {
        for (int i = tid; i < CRAW * CRAW; i += MEGA_TPB) {
            int sy = i / CRAW, sx = i % CRAW;
            int gy = y0 + sy - 3, gx = x0 + sx - 3;
            float v = 0.0f;
            if (gy >= 0 && gy < HH && gx >= 0 && gx < WW) v = img[gy * WW + gx];
            C.raw[sy * CS + sx] = v;
        }
    }
    __syncthreads();

    float rg[7], rdg[7];
#pragma unroll
    for (int k = 0; k < 7; k++) { rg[k] = C.g1[k]; rdg[k] = C.dg1[k]; }

#pragma unroll
    for (int rr = 0; rr < 4; rr++) {
        int r = ty + rr * 8;
#pragma unroll
        for (int half = 0; half < 2; half++) {
            int c = tx + half * 32;
            if (half == 1 && tx >= CRAW - 32) break;
            float pdg = 0.f, pg = 0.f, adg = 0.f, ag = 0.f;
#pragma unroll
            for (int k = 0; k < 7; k++) {
                float v = C.raw[(r + k) * CS + c];
                float a = fabsf(v);
                pdg = fmaf(rdg[k], v, pdg);
                pg  = fmaf(rg[k],  v, pg);
                adg = fmaf(rdg[k], a, adg);
                ag  = fmaf(rg[k],  a, ag);
            }
            C.pdg[r * CS + c] = pdg;
            C.pg [r * CS + c] = pg;
            C.adg[r * CS + c] = adg;
            C.ag [r * CS + c] = ag;
        }
    }
    __syncthreads();

    const int r  = tid >> 3;
    const int cb = (tid & 7) * 4;
    float wpd[10], wpg[10], wad[10], wag[10];
#pragma unroll
    for (int j = 0; j < 10; j++) {
        wpd[j] = C.pdg[r * CS + cb + j];
        wpg[j] = C.pg [r * CS + cb + j];
        wad[j] = C.adg[r * CS + cb + j];
        wag[j] = C.ag [r * CS + cb + j];
    }
    float fy0[4], fx0[4], fy1[4], fx1[4];
#pragma unroll
    for (int u = 0; u < 4; u++) {
        float a = 0.f, bz = 0.f, c = 0.f, d = 0.f;
#pragma unroll
        for (int k = 0; k < 7; k++) {
            a = fmaf(rg[k],  wpd[u + k], a);
            bz= fmaf(rdg[k], wpg[u + k], bz);
            c = fmaf(rg[k],  wad[u + k], c);
            d = fmaf(rdg[k], wag[u + k], d);
        }
        fy0[u] = a * EXTF; fx0[u] = bz * EXTF;
        fy1[u] = c * EXTF; fx1[u] = d * EXTF;
    }
    const size_t base = ((size_t)b * HWSZ + (size_t)(y0 + r) * WW + (x0 + cb)) * 2;
    *(float4*)(g_g  + base)     = make_float4(fy0[0], fx0[0], fy0[1], fx0[1]);
    *(float4*)(g_g  + base + 4) = make_float4(fy0[2], fx0[2], fy0[3], fx0[3]);
    *(float4*)(g_gw + base)     = make_float4(fy1[0], fx1[0], fy1[1], fx1[1]);
    *(float4*)(g_gw + base + 4) = make_float4(fy1[2], fx1[2], fy1[3], fx1[3]);
}

// ---------------- bilinear interp of interleaved 2-channel image -----------
__device__ __forceinline__ void interp2(const float2* __restrict__ img,
                                        float py, float px,
                                        float& v0, float& v1) {
    float y = fminf(fmaxf(py, 0.0f), (float)(HH - 1));
    float x = fminf(fmaxf(px, 0.0f), (float)(WW - 1));
    float y0f = floorf(y), x0f = floorf(x);
    int y0 = (int)y0f, x0 = (int)x0f;
    int y1 = min(y0 + 1, HH - 1);
    int x1 = min(x0 + 1, WW - 1);
    float wy = y - y0f, wx = x - x0f;
    float w00 = (1.0f - wy) * (1.0f - wx);
    float w01 = (1.0f - wy) * wx;
    float w10 = wy * (1.0f - wx);
    float w11 = wy * wx;
    float2 a = img[y0 * WW + x0];
    float2 b = img[y0 * WW + x1];
    float2 c = img[y1 * WW + x0];
    float2 d = img[y1 * WW + x1];
    v0 = a.x * w00 + b.x * w01 + c.x * w10 + d.x * w11;
    v1 = a.y * w00 + b.y * w01 + c.y * w10 + d.y * w11;
}

// ---------------- snake ----------------
__device__ __forceinline__ void snake_run(const float* __restrict__ nodes,
                                          const float* __restrict__ widths,
                                          int b, SmemSnake& S, int tid) {
    const int i = tid;
    const bool act = (i < NN);

    const float2* g  = (const float2*)g_g  + (size_t)b * HWSZ;
    const float2* gw = (const float2*)g_gw + (size_t)b * HWSZ;

    float xy = 0.f, xx = 0.f;
    if (act) {
        xy = nodes[((size_t)b * NN + i) * 2 + 0];
        xx = nodes[((size_t)b * NN + i) * 2 + 1];
        S.xs[0][i][0] = xy; S.xs[0][i][1] = xx;
    }
    __syncthreads();

    const int a2i = max(i - 2, 0), a1 = max(i - 1, 0);
    const int b1 = min(i + 1, NN - 1), b2 = min(i + 2, NN - 1);
    int p = 0;

    for (int s = 0; s < NSTEPS; s++) {
        if (act) {
            float fe0, fe1;
            interp2(g, xy, xx, fe0, fe1);

            float ym2 = S.xs[p][a2i][0], ym1 = S.xs[p][a1][0];
            float yp1 = S.xs[p][b1][0],  yp2 = S.xs[p][b2][0];
            float xm2 = S.xs[p][a2i][1], xm1 = S.xs[p][a1][1];
            float xp1 = S.xs[p][b1][1],  xp2 = S.xs[p][b2][1];

            float d20 = ym1 - 2.0f * xy + yp1;
            float d21 = xm1 - 2.0f * xx + xp1;
            float tm0 = (i >= 1) ? xy : yp1;
            float tm1 = (i >= 1) ? xx : xp1;
            float d2m0 = ym2 - 2.0f * ym1 + tm0;
            float d2m1 = xm2 - 2.0f * xm1 + tm1;
            float tp0 = (i <= NN - 2) ? xy : ym1;
            float tp1 = (i <= NN - 2) ? xx : xm1;
            float d2p0 = tp0 - 2.0f * yp1 + yp2;
            float d2p1 = tp1 - 2.0f * xp1 + xp2;

            float d40 = d2m0 - 2.0f * d20 + d2p0;
            float d41 = d2m1 - 2.0f * d21 + d2p1;

            xy += STEPSZ * (ALPHA_C * d20 - BETA_C * d40 + fe0);
            xx += STEPSZ * (ALPHA_C * d21 - BETA_C * d41 + fe1);
            S.xs[1 - p][i][0] = xy;
            S.xs[1 - p][i][1] = xx;
        }
        __syncthreads();
        p ^= 1;
    }

    if (act) {
        float t0, t1;
        if (i == 0)            { t0 = S.xs[p][1][0] - S.xs[p][0][0];           t1 = S.xs[p][1][1] - S.xs[p][0][1]; }
        else if (i == NN - 1)  { t0 = S.xs[p][NN-1][0] - S.xs[p][NN-2][0];     t1 = S.xs[p][NN-1][1] - S.xs[p][NN-2][1]; }
        else                   { t0 = 0.5f * (S.xs[p][i+1][0] - S.xs[p][i-1][0]); t1 = 0.5f * (S.xs[p][i+1][1] - S.xs[p][i-1][1]); }
        float n0 = -t1, n1 = t0;
        float nrm = sqrtf(n0 * n0 + n1 * n1) + 1e-6f;
        n0 /= nrm; n1 /= nrm;

        float w = widths[(size_t)b * NN + i];
        for (int s = 0; s < NSTEPS_W; s++) {
            float gp0, gp1, gm0, gm1;
            interp2(gw, xy + w * n0, xx + w * n1, gp0, gp1);
            interp2(gw, xy - w * n0, xx - w * n1, gm0, gm1);
            float f = 0.5f * ((gp0 * n0 + gp1 * n1) - (gm0 * n0 + gm1 * n1));
            w = fmaxf(w + STEPSZ * f, 0.5f);
        }
        S.wsh[i] = w;
    }
    __syncthreads();

    if (i < NSEG) {
        float ay = S.xs[p][i][0],   ax = S.xs[p][i][1];
        float by = S.xs[p][i+1][0], bx = S.xs[p][i+1][1];
        float aby = by - ay, abx = bx - ax;
        float den = aby * aby + abx * abx + 1e-8f;
        float aab = ay * aby + ax * abx;
        float a2  = ay * ay + ax * ax;
        float wsg = 0.5f * (S.wsh[i] + S.wsh[i + 1]);
        float4* sp = g_segs + ((size_t)b * NSEG + i) * 3;
        sp[0] = make_float4(aby, abx, aab, 1.0f / den);
        sp[1] = make_float4(den, -2.0f * ay, -2.0f * ax, a2);
        sp[2] = make_float4(wsg, 0.f, 0.f, 0.f);
    }
}

// ---------------- render tile ----------------
__device__ __forceinline__ void render_tile(const float* __restrict__ pred,
                                            float* __restrict__ out,
                                            int b, int bx, int by, int bid,
                                            SmemRender& R, int* s_nk, int* s_last,
                                            int tid) {
    if (tid == 0) *s_nk = 0;
    __syncthreads();

    const float cy = (float)(by * TDIM) + 15.5f;
    const float cx = (float)(bx * TDIM) + 15.5f;
    if (tid < NSEG) {
        const float4* sp = g_segs + ((size_t)b * NSEG + tid) * 3;
        float4 qa = sp[0];
        float4 qb = sp[1];
        float  wsg = sp[2].x;
        float dotpa = fmaf(cy, qa.x, fmaf(cx, qa.y, -qa.z));
        float t = fminf(fmaxf(dotpa * qa.w, 0.0f), 1.0f);
        float pa2 = fmaf(cy, cy, cx * cx) + fmaf(cy, qb.y, fmaf(cx, qb.z, qb.w));
        float dd = fmaf(t, fmaf(t, qb.x, -2.0f * dotpa), pa2);
        float thr = DMAX_C + TILE_RAD + wsg;
        if (dd <= thr * thr) {
            int slot = atomicAdd(s_nk, 1);
            R.ksA[slot] = qa;
            R.ksB[slot] = qb;
            R.ksW[slot] = wsg;
        }
    }
    __syncthreads();
    const int nk = *s_nk;

    const int qy = (tid >> 4);
    const int qx = (tid & 15);
    const int py = by * TDIM + 2 * qy;
    const int px = bx * TDIM + 2 * qx;
    const float fy = (float)py;
    const float fx = (float)px;
    const float p2 = fy * fy + fx * fx;
    const float cx1 = 2.0f * fx + 1.0f;
    const float cy1 = 2.0f * fy + 1.0f;

    float m00 = 3.0e38f, m01 = 3.0e38f, m10 = 3.0e38f, m11 = 3.0e38f;
#pragma unroll 2
    for (int s = 0; s < nk; s++) {
        float4 qa = R.ksA[s];
        float4 qb = R.ksB[s];
        float  wsg = R.ksW[s];
        float d00 = fmaf(fy, qa.x, fmaf(fx, qa.y, -qa.z));
        float d01 = d00 + qa.y;
        float d10 = d00 + qa.x;
        float d11 = d10 + qa.y;
        float q00 = p2 + fmaf(fy, qb.y, fmaf(fx, qb.z, qb.w));
        float ex = cx1 + qb.z;
        float ey = cy1 + qb.y;
        float q01 = q00 + ex;
        float q10 = q00 + ey;
        float q11 = q01 + ey;

        float t00 = fminf(fmaxf(d00 * qa.w, 0.0f), 1.0f);
        float t01 = fminf(fmaxf(d01 * qa.w, 0.0f), 1.0f);
        float t10 = fminf(fmaxf(d10 * qa.w, 0.0f), 1.0f);
        float t11 = fminf(fmaxf(d11 * qa.w, 0.0f), 1.0f);

        float e00 = fmaf(t00, fmaf(t00, qb.x, -2.0f * d00), q00);
        float e01 = fmaf(t01, fmaf(t01, qb.x, -2.0f * d01), q01);
        float e10 = fmaf(t10, fmaf(t10, qb.x, -2.0f * d10), q10);
        float e11 = fmaf(t11, fmaf(t11, qb.x, -2.0f * d11), q11);

        e00 = fmaxf(e00, 1e-18f);
        e01 = fmaxf(e01, 1e-18f);
        e10 = fmaxf(e10, 1e-18f);
        e11 = fmaxf(e11, 1e-18f);
        m00 = fminf(m00, fmaf(e00, rsqrtf(e00), -wsg));
        m01 = fminf(m01, fmaf(e01, rsqrtf(e01), -wsg));
        m10 = fminf(m10, fmaf(e10, rsqrtf(e10), -wsg));
        m11 = fminf(m11, fmaf(e11, rsqrtf(e11), -wsg));
    }

    const float* prow0 = pred + (size_t)b * HWSZ + (size_t)py * WW + px;
    float2 p0 = *(const float2*)prow0;
    float2 p1 = *(const float2*)(prow0 + WW);

    float v = 0.f;
    float dm, df;
    dm = fminf(fmaxf(m00, 0.0f), DMAX_C); df = p0.x - dm; v = fmaf(df, df, v);
    dm = fminf(fmaxf(m01, 0.0f), DMAX_C); df = p0.y - dm; v = fmaf(df, df, v);
    dm = fminf(fmaxf(m10, 0.0f), DMAX_C); df = p1.x - dm; v = fmaf(df, df, v);
    dm = fminf(fmaxf(m11, 0.0f), DMAX_C); df = p1.y - dm; v = fmaf(df, df, v);

#pragma unroll
    for (int o = 16; o > 0; o >>= 1) v += __shfl_down_sync(FULLMASK, v, o);
    if ((tid & 31) == 0) R.wsum[tid >> 5] = v;
    __syncthreads();
    if (tid == 0) {
        float s = 0.f;
#pragma unroll
        for (int i = 0; i < MEGA_TPB / 32; i++) s += R.wsum[i];
        g_part[bid] = s;
        __threadfence();
        unsigned old = atomicAdd(&g_cnt, 1u);
        *s_last = (old == RENDER_TASKS - 1) ? 1 : 0;
    }
    __syncthreads();

    if (*s_last) {
        double a = 0.0;
        for (int i = tid; i < RENDER_TASKS; i += MEGA_TPB)
            a += (double)__ldcg(&g_part[i]);
        R.sd[tid] = a;
        __syncthreads();
#pragma unroll
        for (int s = MEGA_TPB / 2; s > 0; s >>= 1) {
            if (tid < s) R.sd[tid] += R.sd[tid + s];
            __syncthreads();
        }
        if (tid == 0)
            out[0] = (float)(R.sd[0] / (double)((size_t)BB * HWSZ));
    }
    __syncthreads();
}

// ================= mega kernel: throttled task-queue pipeline ===============
__global__ void __launch_bounds__(MEGA_TPB)
mega_kernel(const float* __restrict__ pred,
            const float* __restrict__ nodes,
            const float* __restrict__ widths,
            const float* __restrict__ fltr,
            float* __restrict__ out) {
    __shared__ SmemAll sm;
    __shared__ unsigned int s_task;
    __shared__ int s_nk, s_last;
    const int tid = threadIdx.x;

    for (;;) {
        __syncthreads();
        if (tid == 0) s_task = atomicAdd(&g_task, 1u);
        __syncthreads();
        const unsigned int task = s_task;
        if (task >= NTASKS) return;

        if (task < CONVSNAKE_TASKS) {
            const int b = task / TASKS_PER_BATCH;
            const int t = task % TASKS_PER_BATCH;
            if (t < CTX * CTY) {
                conv_tile(pred, fltr, b, t % CTX, t / CTX, sm.c, tid);
                __threadfence();
                __syncthreads();
                if (tid == 0) atomicAdd(&g_convdone[b * FLAG_STRIDE], 1u);
            } else {
                if (tid == 0) {
                    while (__ldcg(&g_convdone[b * FLAG_STRIDE]) < (unsigned)(CTX * CTY))
                        __nanosleep(300);
                }
                __syncthreads();
                __threadfence();
                snake_run(nodes, widths, b, sm.s, tid);
                __threadfence();
                __syncthreads();
                if (tid == 0) atomicExch(&g_segdone[b * FLAG_STRIDE], 1u);
            }
        } else {
            const int r = (int)(task - CONVSNAKE_TASKS);
            const int b = r / BLKS_PER_IMG;
            const int t = r % BLKS_PER_IMG;
            if (tid == 0) {
                while (__ldcg(&g_segdone[b * FLAG_STRIDE]) == 0u)
                    __nanosleep(500);
            }
            __syncthreads();
            __threadfence();
            render_tile(pred, out, b, t % TILES_X, t / TILES_X, r,
                        sm.r, &s_nk, &s_last, tid);
        }
    }
}

// ---------------- launcher --------------------------------------------------
extern "C" void kernel_launch(void* const* d_in, const int* in_sizes, int n_in,
                              void* d_out, int out_size) {
    const float* pred   = (const float*)d_in[0];
    const float* nodes  = (const float*)d_in[1];
    const float* widths = (const float*)d_in[2];
    const float* fltr   = (const float*)d_in[3];
    float* out = (float*)d_out;

    reset_kernel<<<1, 1>>>();
    mega_kernel<<<MEGA_BLOCKS, MEGA_TPB>>>(pred, nodes, widths, fltr, out);
}

// round 17
// speedup vs baseline: 1.0677x; 1.0419x over previous
#include <cuda_runtime.h>
#include <math.h>

// Problem constants
#define BB      8
#define HH      384
#define WW      384
#define NN      96
#define NSEG    (NN - 1)
#define HWSZ    (HH * WW)
#define STEPSZ  0.1f
#define ALPHA_C 0.01f
#define BETA_C  0.01f
#define NSTEPS  50
#define NSTEPS_W 10
#define DMAX_C  15.0f
#define EXTF    10.0f

// Render: 32x32 pixel tiles, 256 threads, 2x2 px per thread
#define TDIM          32
#define RENDER_TPB    256
#define TILES_X       (WW / TDIM)              // 12
#define TILES_Y       (HH / TDIM)              // 12
#define BLKS_PER_IMG  (TILES_X * TILES_Y)      // 144
#define RENDER_BLKS   (BB * BLKS_PER_IMG)      // 1152
#define TILE_RAD      21.95f

#define FULLMASK 0xffffffffu

// ---------------- device scratch ----------------
// gradients stored CHANNEL-INTERLEAVED: [b][pix][2] (y-grad, x-grad)
__device__ float  g_g [BB * 2 * HWSZ];
__device__ float  g_gw[BB * 2 * HWSZ];
__device__ float4 g_segs[BB * NSEG * 3];
__device__ float  g_part[RENDER_BLKS];
__device__ unsigned int g_cnt = 0;

// ---------------- kernel 1: separable 7x7 conv (structured indexing) -------
#define CT   32
#define CRAW 38
#define CS   41
#define CTX  (WW / CT)   // 12
#define CTY  (HH / CT)   // 12

__global__ void __launch_bounds__(256)
conv_kernel(const float* __restrict__ pred, const float* __restrict__ fltr) {
    __shared__ float s_raw[CRAW * CS];
    __shared__ float s_pdg[CT * CS];
    __shared__ float s_pg [CT * CS];
    __shared__ float s_adg[CT * CS];
    __shared__ float s_ag [CT * CS];
    __shared__ float s_g1[7], s_dg1[7];

    const int b   = blockIdx.z;
    const int x0  = blockIdx.x * CT, y0 = blockIdx.y * CT;
    const int tid = threadIdx.x;
    const int ty  = tid >> 5;
    const int tx  = tid & 31;

    if (tid < 7) {
        float sg = 0.f, sd = 0.f;
#pragma unroll
        for (int k = 0; k < 7; k++) {
            sg += fabsf(fltr[k * 7 + tid]);
            sd += fltr[tid * 7 + k];
        }
        s_g1[tid] = sg;
        s_dg1[tid] = sd;
    }

    const float* img = pred + (size_t)b * HWSZ;
    const bool interior = (blockIdx.x >= 1) && (blockIdx.x <= CTX - 2) &&
                          (blockIdx.y >= 1) && (blockIdx.y <= CTY - 2);
    if (interior) {
        const float* src = img + (y0 - 3) * WW + (x0 - 3);
#pragma unroll
        for (int rr = 0; rr < 5; rr++) {
            int r = ty + rr * 8;
            if (r < CRAW) {
                float*       dst = s_raw + r * CS;
                const float* sr  = src   + r * WW;
                dst[tx] = sr[tx];
                if (tx < CRAW - 32) dst[tx + 32] = sr[tx + 32];
            }
        }
    } else {
        for (int i = tid; i < CRAW * CRAW; i += 256) {
            int sy = i / CRAW, sx = i % CRAW;
            int gy = y0 + sy - 3, gx = x0 + sx - 3;
            float v = 0.0f;
            if (gy >= 0 && gy < HH && gx >= 0 && gx < WW) v = img[gy * WW + gx];
            s_raw[sy * CS + sx] = v;
        }
    }
    __syncthreads();

    float rg[7], rdg[7];
#pragma unroll
    for (int k = 0; k < 7; k++) { rg[k] = s_g1[k]; rdg[k] = s_dg1[k]; }

#pragma unroll
    for (int rr = 0; rr < 4; rr++) {
        int r = ty + rr * 8;
#pragma unroll
        for (int half = 0; half < 2; half++) {
            int c = tx + half * 32;
            if (half == 1 && tx >= CRAW - 32) break;
            float pdg = 0.f, pg = 0.f, adg = 0.f, ag = 0.f;
#pragma unroll
            for (int k = 0; k < 7; k++) {
                float v = s_raw[(r + k) * CS + c];
                float a = fabsf(v);
                pdg = fmaf(rdg[k], v, pdg);
                pg  = fmaf(rg[k],  v, pg);
                adg = fmaf(rdg[k], a, adg);
                ag  = fmaf(rg[k],  a, ag);
            }
            s_pdg[r * CS + c] = pdg;
            s_pg [r * CS + c] = pg;
            s_adg[r * CS + c] = adg;
            s_ag [r * CS + c] = ag;
        }
    }
    __syncthreads();

    const int r  = tid >> 3;
    const int cb = (tid & 7) * 4;
    float wpd[10], wpg[10], wad[10], wag[10];
#pragma unroll
    for (int j = 0; j < 10; j++) {
        wpd[j] = s_pdg[r * CS + cb + j];
        wpg[j] = s_pg [r * CS + cb + j];
        wad[j] = s_adg[r * CS + cb + j];
        wag[j] = s_ag [r * CS + cb + j];
    }
    float fy0[4], fx0[4], fy1[4], fx1[4];
#pragma unroll
    for (int u = 0; u < 4; u++) {
        float a = 0.f, bz = 0.f, c = 0.f, d = 0.f;
#pragma unroll
        for (int k = 0; k < 7; k++) {
            a = fmaf(rg[k],  wpd[u + k], a);
            bz= fmaf(rdg[k], wpg[u + k], bz);
            c = fmaf(rg[k],  wad[u + k], c);
            d = fmaf(rdg[k], wag[u + k], d);
        }
        fy0[u] = a * EXTF; fx0[u] = bz * EXTF;
        fy1[u] = c * EXTF; fx1[u] = d * EXTF;
    }
    const size_t base = ((size_t)b * HWSZ + (size_t)(y0 + r) * WW + (x0 + cb)) * 2;
    *(float4*)(g_g  + base)     = make_float4(fy0[0], fx0[0], fy0[1], fx0[1]);
    *(float4*)(g_g  + base + 4) = make_float4(fy0[2], fx0[2], fy0[3], fx0[3]);
    *(float4*)(g_gw + base)     = make_float4(fy1[0], fx1[0], fy1[1], fx1[1]);
    *(float4*)(g_gw + base + 4) = make_float4(fy1[2], fx1[2], fy1[3], fx1[3]);
}

// ---------------- bilinear interp of interleaved 2-channel image -----------
__device__ __forceinline__ void interp2(const float2* __restrict__ img,
                                        float py, float px,
                                        float& v0, float& v1) {
    float y = fminf(fmaxf(py, 0.0f), (float)(HH - 1));
    float x = fminf(fmaxf(px, 0.0f), (float)(WW - 1));
    float y0f = floorf(y), x0f = floorf(x);
    int y0 = (int)y0f, x0 = (int)x0f;
    int y1 = min(y0 + 1, HH - 1);
    int x1 = min(x0 + 1, WW - 1);
    float wy = y - y0f, wx = x - x0f;
    float w00 = (1.0f - wy) * (1.0f - wx);
    float w01 = (1.0f - wy) * wx;
    float w10 = wy * (1.0f - wx);
    float w11 = wy * wx;
    float2 a = img[y0 * WW + x0];
    float2 b = img[y0 * WW + x1];
    float2 c = img[y1 * WW + x0];
    float2 d = img[y1 * WW + x1];
    v0 = a.x * w00 + b.x * w01 + c.x * w10 + d.x * w11;
    v1 = a.y * w00 + b.y * w01 + c.y * w10 + d.y * w11;
}

// issue phase of interp: compute weights and start the 4 loads
struct InterpState {
    float2 a, b, c, d;
    float w00, w01, w10, w11;
};
__device__ __forceinline__ void interp2_issue(const float2* __restrict__ img,
                                              float py, float px,
                                              InterpState& st) {
    float y = fminf(fmaxf(py, 0.0f), (float)(HH - 1));
    float x = fminf(fmaxf(px, 0.0f), (float)(WW - 1));
    float y0f = floorf(y), x0f = floorf(x);
    int y0 = (int)y0f, x0 = (int)x0f;
    int y1 = min(y0 + 1, HH - 1);
    int x1 = min(x0 + 1, WW - 1);
    float wy = y - y0f, wx = x - x0f;
    st.w00 = (1.0f - wy) * (1.0f - wx);
    st.w01 = (1.0f - wy) * wx;
    st.w10 = wy * (1.0f - wx);
    st.w11 = wy * wx;
    st.a = __ldg(img + y0 * WW + x0);
    st.b = __ldg(img + y0 * WW + x1);
    st.c = __ldg(img + y1 * WW + x0);
    st.d = __ldg(img + y1 * WW + x1);
}
__device__ __forceinline__ void interp2_combine(const InterpState& st,
                                                float& v0, float& v1) {
    v0 = st.a.x * st.w00 + st.b.x * st.w01 + st.c.x * st.w10 + st.d.x * st.w11;
    v1 = st.a.y * st.w00 + st.b.y * st.w01 + st.c.y * st.w10 + st.d.y * st.w11;
}

// ---------------- kernel 2: snake, software-pipelined interp ---------------
// Loads for step s+1 are issued BEFORE the step-s barrier, so LDG latency
// overlaps the barrier + stencil of the next step. Math order identical.
__global__ void snake_kernel(const float* __restrict__ nodes,
                             const float* __restrict__ widths) {
    const int b = blockIdx.x;
    const int i = threadIdx.x;
    const bool act = (i < NN);

    __shared__ float xs[2][NN][2];
    __shared__ float wsh[NN];

    const float2* g  = (const float2*)g_g  + (size_t)b * HWSZ;
    const float2* gw = (const float2*)g_gw + (size_t)b * HWSZ;

    float xy = 0.f, xx = 0.f;
    InterpState st;
    if (act) {
        xy = nodes[((size_t)b * NN + i) * 2 + 0];
        xx = nodes[((size_t)b * NN + i) * 2 + 1];
        xs[0][i][0] = xy; xs[0][i][1] = xx;
        interp2_issue(g, xy, xx, st);   // loads for step 0 in flight
    }
    __syncthreads();

    const int a2i = max(i - 2, 0), a1 = max(i - 1, 0);
    const int b1 = min(i + 1, NN - 1), b2 = min(i + 2, NN - 1);
    int p = 0;

    for (int s = 0; s < NSTEPS; s++) {
        if (act) {
            // stencil from barrier-protected positions (overlaps the in-flight loads)
            float ym2 = xs[p][a2i][0], ym1 = xs[p][a1][0];
            float yp1 = xs[p][b1][0],  yp2 = xs[p][b2][0];
            float xm2 = xs[p][a2i][1], xm1 = xs[p][a1][1];
            float xp1 = xs[p][b1][1],  xp2 = xs[p][b2][1];

            float d20 = ym1 - 2.0f * xy + yp1;
            float d21 = xm1 - 2.0f * xx + xp1;
            float tm0 = (i >= 1) ? xy : yp1;
            float tm1 = (i >= 1) ? xx : xp1;
            float d2m0 = ym2 - 2.0f * ym1 + tm0;
            float d2m1 = xm2 - 2.0f * xm1 + tm1;
            float tp0 = (i <= NN - 2) ? xy : ym1;
            float tp1 = (i <= NN - 2) ? xx : xm1;
            float d2p0 = tp0 - 2.0f * yp1 + yp2;
            float d2p1 = tp1 - 2.0f * xp1 + xp2;

            float d40 = d2m0 - 2.0f * d20 + d2p0;
            float d41 = d2m1 - 2.0f * d21 + d2p1;

            float fe0, fe1;
            interp2_combine(st, fe0, fe1);   // consume pipelined loads

            xy += STEPSZ * (ALPHA_C * d20 - BETA_C * d40 + fe0);
            xx += STEPSZ * (ALPHA_C * d21 - BETA_C * d41 + fe1);
            xs[1 - p][i][0] = xy;
            xs[1 - p][i][1] = xx;

            interp2_issue(g, xy, xx, st);    // loads for step s+1 (before barrier)
        }
        __syncthreads();
        p ^= 1;
    }

    if (act) {
        float t0, t1;
        if (i == 0)            { t0 = xs[p][1][0] - xs[p][0][0];           t1 = xs[p][1][1] - xs[p][0][1]; }
        else if (i == NN - 1)  { t0 = xs[p][NN-1][0] - xs[p][NN-2][0];     t1 = xs[p][NN-1][1] - xs[p][NN-2][1]; }
        else                   { t0 = 0.5f * (xs[p][i+1][0] - xs[p][i-1][0]); t1 = 0.5f * (xs[p][i+1][1] - xs[p][i-1][1]); }
        float n0 = -t1, n1 = t0;
        float nrm = sqrtf(n0 * n0 + n1 * n1) + 1e-6f;
        n0 /= nrm; n1 /= nrm;

        float w = widths[(size_t)b * NN + i];
        for (int s = 0; s < NSTEPS_W; s++) {
            float gp0, gp1, gm0, gm1;
            interp2(gw, xy + w * n0, xx + w * n1, gp0, gp1);
            interp2(gw, xy - w * n0, xx - w * n1, gm0, gm1);
            float f = 0.5f * ((gp0 * n0 + gp1 * n1) - (gm0 * n0 + gm1 * n1));
            w = fmaxf(w + STEPSZ * f, 0.5f);
        }
        wsh[i] = w;
    }
    __syncthreads();

    if (i < NSEG) {
        float ay = xs[p][i][0],   ax = xs[p][i][1];
        float by = xs[p][i+1][0], bx = xs[p][i+1][1];
        float aby = by - ay, abx = bx - ax;
        float den = aby * aby + abx * abx + 1e-8f;
        float aab = ay * aby + ax * abx;
        float a2  = ay * ay + ax * ax;
        float wsg = 0.5f * (wsh[i] + wsh[i + 1]);
        float4* sp = g_segs + ((size_t)b * NSEG + i) * 3;
        sp[0] = make_float4(aby, abx, aab, 1.0f / den);
        sp[1] = make_float4(den, -2.0f * ay, -2.0f * ax, a2);
        sp[2] = make_float4(wsg, 0.f, 0.f, 0.f);
    }
}

// ---------------- kernel 3: culled render, 2x2 px/thread, fused reduction --
__global__ void __launch_bounds__(RENDER_TPB)
render_kernel(const float* __restrict__ pred, float* __restrict__ out) {
    __shared__ float4 ksA[NSEG];
    __shared__ float4 ksB[NSEG];
    __shared__ float  ksW[NSEG];
    __shared__ int    s_nk;
    __shared__ int    s_last;
    __shared__ float  wsum[RENDER_TPB / 32];
    __shared__ double sd[RENDER_TPB];

    const int tid = threadIdx.x;
    const int bx = blockIdx.x, by = blockIdx.y, b = blockIdx.z;
    const int bid = (b * TILES_Y + by) * TILES_X + bx;

    if (tid == 0) s_nk = 0;
    __syncthreads();

    const float cy = (float)(by * TDIM) + 15.5f;
    const float cx = (float)(bx * TDIM) + 15.5f;
    if (tid < NSEG) {
        const float4* sp = g_segs + ((size_t)b * NSEG + tid) * 3;
        float4 qa = sp[0];
        float4 qb = sp[1];
        float  wsg = sp[2].x;
        float dotpa = fmaf(cy, qa.x, fmaf(cx, qa.y, -qa.z));
        float t = fminf(fmaxf(dotpa * qa.w, 0.0f), 1.0f);
        float pa2 = fmaf(cy, cy, cx * cx) + fmaf(cy, qb.y, fmaf(cx, qb.z, qb.w));
        float dd = fmaf(t, fmaf(t, qb.x, -2.0f * dotpa), pa2);
        float thr = DMAX_C + TILE_RAD + wsg;
        if (dd <= thr * thr) {
            int slot = atomicAdd(&s_nk, 1);
            ksA[slot] = qa;
            ksB[slot] = qb;
            ksW[slot] = wsg;
        }
    }
    __syncthreads();
    const int nk = s_nk;

    const int qy = (tid >> 4);
    const int qx = (tid & 15);
    const int py = by * TDIM + 2 * qy;
    const int px = bx * TDIM + 2 * qx;
    const float fy = (float)py;
    const float fx = (float)px;
    const float p2 = fy * fy + fx * fx;
    const float cx1 = 2.0f * fx + 1.0f;
    const float cy1 = 2.0f * fy + 1.0f;

    float m00 = 3.0e38f, m01 = 3.0e38f, m10 = 3.0e38f, m11 = 3.0e38f;
#pragma unroll 2
    for (int s = 0; s < nk; s++) {
        float4 qa = ksA[s];
        float4 qb = ksB[s];
        float  wsg = ksW[s];
        float d00 = fmaf(fy, qa.x, fmaf(fx, qa.y, -qa.z));
        float d01 = d00 + qa.y;
        float d10 = d00 + qa.x;
        float d11 = d10 + qa.y;
        float q00 = p2 + fmaf(fy, qb.y, fmaf(fx, qb.z, qb.w));
        float ex = cx1 + qb.z;
        float ey = cy1 + qb.y;
        float q01 = q00 + ex;
        float q10 = q00 + ey;
        float q11 = q01 + ey;

        float t00 = fminf(fmaxf(d00 * qa.w, 0.0f), 1.0f);
        float t01 = fminf(fmaxf(d01 * qa.w, 0.0f), 1.0f);
        float t10 = fminf(fmaxf(d10 * qa.w, 0.0f), 1.0f);
        float t11 = fminf(fmaxf(d11 * qa.w, 0.0f), 1.0f);

        float e00 = fmaf(t00, fmaf(t00, qb.x, -2.0f * d00), q00);
        float e01 = fmaf(t01, fmaf(t01, qb.x, -2.0f * d01), q01);
        float e10 = fmaf(t10, fmaf(t10, qb.x, -2.0f * d10), q10);
        float e11 = fmaf(t11, fmaf(t11, qb.x, -2.0f * d11), q11);

        e00 = fmaxf(e00, 1e-18f);
        e01 = fmaxf(e01, 1e-18f);
        e10 = fmaxf(e10, 1e-18f);
        e11 = fmaxf(e11, 1e-18f);
        m00 = fminf(m00, fmaf(e00, rsqrtf(e00), -wsg));
        m01 = fminf(m01, fmaf(e01, rsqrtf(e01), -wsg));
        m10 = fminf(m10, fmaf(e10, rsqrtf(e10), -wsg));
        m11 = fminf(m11, fmaf(e11, rsqrtf(e11), -wsg));
    }

    const float* prow0 = pred + (size_t)b * HWSZ + (size_t)py * WW + px;
    float2 p0 = *(const float2*)prow0;
    float2 p1 = *(const float2*)(prow0 + WW);

    float v = 0.f;
    float dm, df;
    dm = fminf(fmaxf(m00, 0.0f), DMAX_C); df = p0.x - dm; v = fmaf(df, df, v);
    dm = fminf(fmaxf(m01, 0.0f), DMAX_C); df = p0.y - dm; v = fmaf(df, df, v);
    dm = fminf(fmaxf(m10, 0.0f), DMAX_C); df = p1.x - dm; v = fmaf(df, df, v);
    dm = fminf(fmaxf(m11, 0.0f), DMAX_C); df = p1.y - dm; v = fmaf(df, df, v);

#pragma unroll
    for (int o = 16; o > 0; o >>= 1) v += __shfl_down_sync(FULLMASK, v, o);
    if ((tid & 31) == 0) wsum[tid >> 5] = v;
    __syncthreads();
    if (tid == 0) {
        float s = 0.f;
#pragma unroll
        for (int i = 0; i < RENDER_TPB / 32; i++) s += wsum[i];
        g_part[bid] = s;
        __threadfence();
        unsigned old = atomicAdd(&g_cnt, 1u);
        s_last = (old == RENDER_BLKS - 1) ? 1 : 0;
    }
    __syncthreads();

    if (s_last) {
        double a = 0.0;
        for (int i = tid; i < RENDER_BLKS; i += RENDER_TPB)
            a += (double)__ldcg(&g_part[i]);
        sd[tid] = a;
        __syncthreads();
#pragma unroll
        for (int s = RENDER_TPB / 2; s > 0; s >>= 1) {
            if (tid < s) sd[tid] += sd[tid + s];
            __syncthreads();
        }
        if (tid == 0) {
            out[0] = (float)(sd[0] / (double)((size_t)BB * HWSZ));
            g_cnt = 0;
        }
    }
}

// ---------------- launcher --------------------------------------------------
extern "C" void kernel_launch(void* const* d_in, const int* in_sizes, int n_in,
                              void* d_out, int out_size) {
    const float* pred   = (const float*)d_in[0];
    const float* nodes  = (const float*)d_in[1];
    const float* widths = (const float*)d_in[2];
    const float* fltr   = (const float*)d_in[3];
    float* out = (float*)d_out;

    dim3 cgrid(CTX, CTY, BB);
    conv_kernel<<<cgrid, 256>>>(pred, fltr);

    snake_kernel<<<BB, 128>>>(nodes, widths);

    dim3 rgrid(TILES_X, TILES_Y, BB);
    render_kernel<<<rgrid, RENDER_TPB>>>(pred, out);
}